// round 6
// baseline (speedup 1.0000x reference)
#include <cuda_runtime.h>
#include <stdint.h>

// Banded outer product: out[b,i,j] = s[b,i]*e[b,j] for 0 <= j-i <= 15, else 0.
// B=16, L=4096. Output 1.073 GB fp32 -> pure HBM-store-bound (7.0 TB/s, 85.5%).
//
// R6: 4 rows per block (64 KB stores/block), fully unrolled, no loop-carried
// dependence (unlike R2's serialized 55-iter grid-stride). Tests whether CTA
// churn (block lifetime ~600 cyc in R1/R5) is what caps DRAM at 85.5%.
// Phase 1: unconditional zero-fill of all chunks. Phase 2: owning threads
// overwrite the <=5 band chunks per row (same thread+address -> ordered).

#define LDIM 4096
#define BAND 15
#define RPB  4          // rows per block (4 | LDIM, so one batch per block)

__global__ __launch_bounds__(256, 8)
void band_outer_kernel(const float* __restrict__ s,
                       const float* __restrict__ e,
                       float* __restrict__ out)
{
    const int row0 = blockIdx.x * RPB;       // first row: b*L + i0
    const int i0   = row0 & (LDIM - 1);      // rows i0..i0+3, same batch
    const int t    = threadIdx.x;

    // all row scalars up front: latency hides under the zero stores
    float sv[RPB];
#pragma unroll
    for (int r = 0; r < RPB; ++r) sv[r] = __ldg(&s[row0 + r]);

    const float* __restrict__ erow = e + (row0 & ~(LDIM - 1));
    float4* __restrict__ obase =
        reinterpret_cast<float4*>(out) + (size_t)row0 * (LDIM / 4);

    // ---- phase 1: unconditional zero fill, 16 independent STG.128/thread ----
    const float4 z = make_float4(0.f, 0.f, 0.f, 0.f);
#pragma unroll
    for (int r = 0; r < RPB; ++r) {
#pragma unroll
        for (int k = 0; k < 4; ++k) {
            __stcs(&obase[(size_t)r * (LDIM / 4) + t + k * 256], z);
        }
    }

    // ---- phase 2: overwrite band chunks (<=5 per row) ----
#pragma unroll
    for (int r = 0; r < RPB; ++r) {
        const int i   = i0 + r;
        const int lo4 = i >> 2;
        const int hi4 = (i + BAND) >> 2;     // c4 <= 1023 always
        const float sr = sv[r];

#pragma unroll
        for (int k = 0; k < 4; ++k) {
            const int c4 = t + k * 256;
            if (c4 >= lo4 && c4 <= hi4) {
                const int j = c4 << 2;
                float4 v;
                v.x = ((unsigned)(j     - i) <= BAND) ? sr * __ldg(&erow[j])     : 0.f;
                v.y = ((unsigned)(j + 1 - i) <= BAND) ? sr * __ldg(&erow[j + 1]) : 0.f;
                v.z = ((unsigned)(j + 2 - i) <= BAND) ? sr * __ldg(&erow[j + 2]) : 0.f;
                v.w = ((unsigned)(j + 3 - i) <= BAND) ? sr * __ldg(&erow[j + 3]) : 0.f;
                __stcs(&obase[(size_t)r * (LDIM / 4) + c4], v);  // same owner -> ordered
            }
        }
    }
}

extern "C" void kernel_launch(void* const* d_in, const int* in_sizes, int n_in,
                              void* d_out, int out_size)
{
    const float* s = (const float*)d_in[0];
    const float* e = (const float*)d_in[1];
    float* out = (float*)d_out;

    band_outer_kernel<<<(16 * LDIM) / RPB, 256>>>(s, e, out);
}

// round 8
// speedup vs baseline: 1.0511x; 1.0511x over previous
#include <cuda_runtime.h>
#include <stdint.h>

// Banded outer product: out[b,i,j] = s[b,i]*e[b,j] for 0 <= j-i <= 15, else 0.
// B=16, L=4096. Output 1.073 GB fp32 -> pure HBM-store-bound.
//
// R8 = R7 resubmit (R7 bench was a broker infra failure, no data).
// Granularity trend: 1184 blk: 71% | 16384: 81% | 65536: 85.5% DRAM.
// One step finer: HALF a row per block, 131072 blocks x 256 thr x 2 float4
// (8 KB/block). Zero-fill first, then owning threads overwrite the <=5 band
// chunks if they fall in this half (same thread+address -> ordered).

#define LDIM 4096
#define BAND 15

__global__ __launch_bounds__(256, 8)
void band_outer_kernel(const float* __restrict__ s,
                       const float* __restrict__ e,
                       float* __restrict__ out)
{
    const unsigned blk = blockIdx.x;
    const int row  = blk >> 1;               // b*L + i
    const int half = blk & 1;                // 0: chunks [0,511], 1: [512,1023]
    const int i    = row & (LDIM - 1);
    const int t    = threadIdx.x;

    const float sv = __ldg(&s[row]);
    const float* __restrict__ erow = e + (row & ~(LDIM - 1));

    float4* __restrict__ orow =
        reinterpret_cast<float4*>(out) + (size_t)row * (LDIM / 4);

    const int cbase = half << 9;              // 0 or 512

    // ---- phase 1: unconditional zero fill (2 independent STG.128/thread) ----
    const float4 z = make_float4(0.f, 0.f, 0.f, 0.f);
    __stcs(&orow[cbase + t],       z);
    __stcs(&orow[cbase + t + 256], z);

    // ---- phase 2: overwrite band chunks if they land in this half ----
    const int lo4 = i >> 2;
    const int hi4 = (i + BAND) >> 2;          // <= 1023 always

#pragma unroll
    for (int k = 0; k < 2; ++k) {
        const int c4 = cbase + t + k * 256;
        if (c4 >= lo4 && c4 <= hi4) {
            const int j = c4 << 2;
            float4 v;
            v.x = ((unsigned)(j     - i) <= BAND) ? sv * __ldg(&erow[j])     : 0.f;
            v.y = ((unsigned)(j + 1 - i) <= BAND) ? sv * __ldg(&erow[j + 1]) : 0.f;
            v.z = ((unsigned)(j + 2 - i) <= BAND) ? sv * __ldg(&erow[j + 2]) : 0.f;
            v.w = ((unsigned)(j + 3 - i) <= BAND) ? sv * __ldg(&erow[j + 3]) : 0.f;
            __stcs(&orow[c4], v);   // same thread as the zero store -> ordered
        }
    }
}

extern "C" void kernel_launch(void* const* d_in, const int* in_sizes, int n_in,
                              void* d_out, int out_size)
{
    const float* s = (const float*)d_in[0];
    const float* e = (const float*)d_in[1];
    float* out = (float*)d_out;

    // 2 blocks per row, 16*4096 rows
    band_outer_kernel<<<2 * 16 * LDIM, 256>>>(s, e, out);
}